// round 2
// baseline (speedup 1.0000x reference)
#include <cuda_runtime.h>

// Problem constants
#define N_CLS 64
#define K_SHOT 64
#define D_DIM 640
#define Q_PER 2048
#define NQ (N_CLS * Q_PER)        // 131072 query rows
#define SUP_ROWS (N_CLS * K_SHOT) // 4096 support rows

typedef unsigned long long ull;

// Transposed, normalized prototypes: g_Pt[d * 64 + n] = prototypes[n][d]
__device__ __align__(16) float g_Pt[D_DIM * N_CLS];

// ---------------- packed f32x2 helpers (sm_100+) ----------------
__device__ __forceinline__ ull pack2(float x, float y) {
    ull r;
    asm("mov.b64 %0, {%1, %2};" : "=l"(r) : "f"(x), "f"(y));
    return r;
}
__device__ __forceinline__ void unpack2(ull v, float &x, float &y) {
    asm("mov.b64 {%0, %1}, %2;" : "=f"(x), "=f"(y) : "l"(v));
}
__device__ __forceinline__ void ffma2(ull &d, ull a, ull b) {
    asm("fma.rn.f32x2 %0, %1, %2, %0;" : "+l"(d) : "l"(a), "l"(b));
}
__device__ __forceinline__ void cp16(unsigned dst, const void* src) {
    asm volatile("cp.async.cg.shared.global [%0], [%1], 16;" :: "r"(dst), "l"(src));
}

// ======================================================================
// Kernel 1: per-class prototype computation. One block per class i.
// (unchanged from R1 — ~4% of runtime)
// ======================================================================
__global__ void __launch_bounds__(256) proto_kernel(const float* __restrict__ emb) {
    const int i    = blockIdx.x;
    const int tid  = threadIdx.x;
    const int lane = tid & 31;
    const int wid  = tid >> 5;

    __shared__ float s_pu[D_DIM];
    __shared__ float s_w[64];
    __shared__ float s_red[8];
    __shared__ float s_pn, s_isum, s_inorm;

    // ---- proto_unnorm (strided mean) + its squared norm ----
    float pn2 = 0.f;
    for (int d = tid; d < D_DIM; d += 256) {
        float s = 0.f;
        #pragma unroll 8
        for (int k = 0; k < K_SHOT; ++k)
            s += emb[(size_t)(k * N_CLS + i) * D_DIM + d];
        s *= (1.0f / 64.0f);
        s_pu[d] = s;
        pn2 += s * s;
    }
    #pragma unroll
    for (int o = 16; o; o >>= 1) pn2 += __shfl_xor_sync(0xffffffffu, pn2, o);
    if (lane == 0) s_red[wid] = pn2;
    __syncthreads();
    if (tid == 0) {
        float t = 0.f;
        #pragma unroll
        for (int w = 0; w < 8; ++w) t += s_red[w];
        s_pn = fmaxf(sqrtf(t), 1e-8f);
    }
    __syncthreads();
    const float p_norm = s_pn;

    // ---- per-shot cosine-similarity dis[j] ----
    const float* blk = emb + (size_t)i * 64 * D_DIM;
    for (int j = wid; j < 64; j += 8) {
        const float* row = blk + (size_t)j * D_DIM;
        float dot = 0.f, s2 = 0.f;
        for (int d = lane; d < D_DIM; d += 32) {
            float a = row[d];
            dot += a * s_pu[d];
            s2  += a * a;
        }
        #pragma unroll
        for (int o = 16; o; o >>= 1) {
            dot += __shfl_xor_sync(0xffffffffu, dot, o);
            s2  += __shfl_xor_sync(0xffffffffu, s2, o);
        }
        if (lane == 0) {
            float sn = fmaxf(sqrtf(s2), 1e-8f);
            s_w[j] = expf(dot / (p_norm * sn));
        }
    }
    __syncthreads();

    // ---- softmax denominator ----
    if (tid < 32) {
        float v = s_w[tid] + s_w[tid + 32];
        #pragma unroll
        for (int o = 16; o; o >>= 1) v += __shfl_xor_sync(0xffffffffu, v, o);
        if (tid == 0) s_isum = 1.0f / v;
    }
    __syncthreads();
    const float inv_sum = s_isum;

    // ---- weighted prototype + normalization ----
    float pd0 = 0.f, pd1 = 0.f, pd2 = 0.f;
    const int d0 = tid, d1 = tid + 256, d2 = tid + 512;
    for (int j = 0; j < 64; ++j) {
        float wj = s_w[j] * inv_sum;
        const float* row = blk + (size_t)j * D_DIM;
        pd0 += wj * row[d0];
        pd1 += wj * row[d1];
        if (d2 < D_DIM) pd2 += wj * row[d2];
    }
    float q2 = pd0 * pd0 + pd1 * pd1 + ((d2 < D_DIM) ? pd2 * pd2 : 0.f);
    #pragma unroll
    for (int o = 16; o; o >>= 1) q2 += __shfl_xor_sync(0xffffffffu, q2, o);
    __syncthreads();
    if (lane == 0) s_red[wid] = q2;
    __syncthreads();
    if (tid == 0) {
        float t = 0.f;
        #pragma unroll
        for (int w = 0; w < 8; ++w) t += s_red[w];
        s_inorm = 1.0f / fmaxf(sqrtf(t), 1e-12f);
    }
    __syncthreads();
    const float innorm = s_inorm;

    g_Pt[d0 * N_CLS + i] = pd0 * innorm;
    g_Pt[d1 * N_CLS + i] = pd1 * innorm;
    if (d2 < D_DIM) g_Pt[d2 * N_CLS + i] = pd2 * innorm;
}

// ======================================================================
// Kernel 2: logits = query @ P^T * 10
//   M-tile 256, K-tile 16, double-buffered via cp.async.
//   Thread tile: 4 rows x 16 cols (rows rg, rg+64, rg+128, rg+192;
//   cols cg*16..+15, cg = tid&3). 32 FFMA2 per k-step vs
//   4 LDS.32 + 2 LDS.128 + 4 pack.
//   Q smem: 256x16 floats, float4-slot XOR swizzle (kq ^ ((r>>1)&3))
//   -> conflict-free reads AND 16B-aligned cp.async dst.
// ======================================================================
#define KT 16
#define NT (D_DIM / KT)   // 40 k-tiles

__global__ void __launch_bounds__(256, 2) logits_kernel(const float* __restrict__ qry,
                                                        float* __restrict__ out) {
    __shared__ __align__(16) float sQ[2][256 * KT];
    __shared__ __align__(16) float sP[2][KT * 64];

    const int tid = threadIdx.x;
    const int cg  = tid & 3;          // column group: cols [cg*16, cg*16+16)
    const int rg  = tid >> 2;         // base row 0..63; rows rg + 64*u
    const int hr  = (rg >> 1) & 3;    // per-thread Q swizzle key
    const size_t rowBase = (size_t)blockIdx.x * 256;

    const unsigned sQs = (unsigned)__cvta_generic_to_shared(&sQ[0][0]);
    const unsigned sPs = (unsigned)__cvta_generic_to_shared(&sP[0][0]);

    // staging indices (4 Q float4s + 1 P float4 per thread per tile)
    const int sr0 = tid >> 2;                 // Q rows r, via f4 = tid + jj*256
    // per-thread P src/dst
    const unsigned pdst0 = sPs + tid * 16;

    ull acc[4][8];
    #pragma unroll
    for (int u = 0; u < 4; ++u)
        #pragma unroll
        for (int m = 0; m < 8; ++m) acc[u][m] = 0ull;

    // ---- stage tile t into buffer b ----
    auto stage = [&](int t, int b) {
        const int kk = t * KT;
        #pragma unroll
        for (int jj = 0; jj < 4; ++jj) {
            const int f4 = tid + jj * 256;     // 0..1023
            const int r  = f4 >> 2;            // 0..255
            const int kq = f4 & 3;             // float4 slot within row
            const float* src = qry + (rowBase + r) * D_DIM + kk + kq * 4;
            const unsigned dst = sQs + (unsigned)b * (256 * KT * 4)
                               + (unsigned)(r * KT + ((kq ^ ((r >> 1) & 3)) << 2)) * 4;
            cp16(dst, src);
        }
        cp16(pdst0 + (unsigned)b * (KT * 64 * 4), g_Pt + (size_t)kk * 64 + tid * 4);
        asm volatile("cp.async.commit_group;" ::: "memory");
    };

    stage(0, 0);

    for (int t = 0; t < NT; ++t) {
        const int b = t & 1;
        if (t + 1 < NT) {
            stage(t + 1, b ^ 1);
            asm volatile("cp.async.wait_group 1;" ::: "memory");
        } else {
            asm volatile("cp.async.wait_group 0;" ::: "memory");
        }
        __syncthreads();

        const float* q0 = &sQ[b][(rg      ) * KT];
        const float* q1 = &sQ[b][(rg +  64) * KT];
        const float* q2 = &sQ[b][(rg + 128) * KT];
        const float* q3 = &sQ[b][(rg + 192) * KT];
        const float* pb = &sP[b][cg * 16];

        #pragma unroll 4
        for (int kp = 0; kp < KT; ++kp) {
            const int col = ((((kp >> 2) ^ hr) << 2) | (kp & 3));
            const ull a0 = pack2(q0[col], q0[col]);
            const ull a1 = pack2(q1[col], q1[col]);
            const ull a2 = pack2(q2[col], q2[col]);
            const ull a3 = pack2(q3[col], q3[col]);
            const ull* pr = (const ull*)(pb + kp * 64);  // 8 col-pairs (2x LDS.128)
            #pragma unroll
            for (int m = 0; m < 8; ++m) {
                const ull p = pr[m];
                ffma2(acc[0][m], a0, p);
                ffma2(acc[1][m], a1, p);
                ffma2(acc[2][m], a2, p);
                ffma2(acc[3][m], a3, p);
            }
        }
        __syncthreads();
    }

    // ---- epilogue: scale by 1/TAU = 10, float4 stores ----
    const float sc = 10.0f;
    #pragma unroll
    for (int u = 0; u < 4; ++u) {
        float* orow = out + (rowBase + rg + 64 * u) * 64 + cg * 16;
        #pragma unroll
        for (int m = 0; m < 4; ++m) {
            float x, y, z, w;
            unpack2(acc[u][2 * m],     x, y);
            unpack2(acc[u][2 * m + 1], z, w);
            *(float4*)(orow + 4 * m) = make_float4(x * sc, y * sc, z * sc, w * sc);
        }
    }
}

// ======================================================================
extern "C" void kernel_launch(void* const* d_in, const int* in_sizes, int n_in,
                              void* d_out, int out_size) {
    const float* emb = (const float*)d_in[0];
    float* out = (float*)d_out;

    // Phase 1: prototypes (writes g_Pt) — one block per class
    proto_kernel<<<N_CLS, 256>>>(emb);

    // Phase 2: logits GEMM over the 131072 query rows
    const float* qry = emb + (size_t)SUP_ROWS * D_DIM;
    logits_kernel<<<NQ / 256, 256>>>(qry, out);
}

// round 4
// speedup vs baseline: 3.9994x; 3.9994x over previous
#include <cuda_runtime.h>
#include <cstdint>

// Problem constants
#define N_CLS 64
#define K_SHOT 64
#define D_DIM 640
#define Q_PER 2048
#define NQ (N_CLS * Q_PER)        // 131072 query rows
#define SUP_ROWS (N_CLS * K_SHOT) // 4096 support rows

// Prototypes pre-packed in mma.m16n8k8 B-fragment lane order, tf32-rounded:
//   g_Pf[(((s*8 + j)*32 + lane)*2 + e] = tf32(P[n][k]),
//   k = 8s + (lane&3) + 4e,  n = 8j + (lane>>2),  s = 0..79, j = 0..7.
__device__ __align__(16) float g_Pf[80 * 8 * 32 * 2];   // 160 KB

// ---------------- helpers ----------------
__device__ __forceinline__ uint32_t tf32_rna(float x) {
    uint32_t r;
    asm("cvt.rna.tf32.f32 %0, %1;" : "=r"(r) : "f"(x));
    return r;
}
__device__ __forceinline__ void cp16(uint32_t dst, const void* src) {
    asm volatile("cp.async.cg.shared.global [%0], [%1], 16;" :: "r"(dst), "l"(src));
}
#define CP_COMMIT() asm volatile("cp.async.commit_group;" ::: "memory")
#define CP_WAIT(n)  asm volatile("cp.async.wait_group %0;" :: "n"(n) : "memory")

__device__ __forceinline__ void mma_tf32(float* d, const uint32_t* a, uint32_t b0, uint32_t b1) {
    asm volatile(
        "mma.sync.aligned.m16n8k8.row.col.f32.tf32.tf32.f32 "
        "{%0,%1,%2,%3}, {%4,%5,%6,%7}, {%8,%9}, {%0,%1,%2,%3};"
        : "+f"(d[0]), "+f"(d[1]), "+f"(d[2]), "+f"(d[3])
        : "r"(a[0]), "r"(a[1]), "r"(a[2]), "r"(a[3]), "r"(b0), "r"(b1));
}

// ======================================================================
// Kernel 1: per-class prototype computation. One block per class i.
// Same math as before; output written tf32-rounded into fragment layout.
// ======================================================================
__global__ void __launch_bounds__(256) proto_kernel(const float* __restrict__ emb) {
    const int i    = blockIdx.x;
    const int tid  = threadIdx.x;
    const int lane = tid & 31;
    const int wid  = tid >> 5;

    __shared__ float s_pu[D_DIM];
    __shared__ float s_w[64];
    __shared__ float s_red[8];
    __shared__ float s_pn, s_isum, s_inorm;

    float pn2 = 0.f;
    for (int d = tid; d < D_DIM; d += 256) {
        float s = 0.f;
        #pragma unroll 8
        for (int k = 0; k < K_SHOT; ++k)
            s += emb[(size_t)(k * N_CLS + i) * D_DIM + d];
        s *= (1.0f / 64.0f);
        s_pu[d] = s;
        pn2 += s * s;
    }
    #pragma unroll
    for (int o = 16; o; o >>= 1) pn2 += __shfl_xor_sync(0xffffffffu, pn2, o);
    if (lane == 0) s_red[wid] = pn2;
    __syncthreads();
    if (tid == 0) {
        float t = 0.f;
        #pragma unroll
        for (int w = 0; w < 8; ++w) t += s_red[w];
        s_pn = fmaxf(sqrtf(t), 1e-8f);
    }
    __syncthreads();
    const float p_norm = s_pn;

    const float* blk = emb + (size_t)i * 64 * D_DIM;
    for (int j = wid; j < 64; j += 8) {
        const float* row = blk + (size_t)j * D_DIM;
        float dot = 0.f, s2 = 0.f;
        for (int d = lane; d < D_DIM; d += 32) {
            float a = row[d];
            dot += a * s_pu[d];
            s2  += a * a;
        }
        #pragma unroll
        for (int o = 16; o; o >>= 1) {
            dot += __shfl_xor_sync(0xffffffffu, dot, o);
            s2  += __shfl_xor_sync(0xffffffffu, s2, o);
        }
        if (lane == 0) {
            float sn = fmaxf(sqrtf(s2), 1e-8f);
            s_w[j] = expf(dot / (p_norm * sn));
        }
    }
    __syncthreads();

    if (tid < 32) {
        float v = s_w[tid] + s_w[tid + 32];
        #pragma unroll
        for (int o = 16; o; o >>= 1) v += __shfl_xor_sync(0xffffffffu, v, o);
        if (tid == 0) s_isum = 1.0f / v;
    }
    __syncthreads();
    const float inv_sum = s_isum;

    float pd0 = 0.f, pd1 = 0.f, pd2 = 0.f;
    const int d0 = tid, d1 = tid + 256, d2 = tid + 512;
    for (int j = 0; j < 64; ++j) {
        float wj = s_w[j] * inv_sum;
        const float* row = blk + (size_t)j * D_DIM;
        pd0 += wj * row[d0];
        pd1 += wj * row[d1];
        if (d2 < D_DIM) pd2 += wj * row[d2];
    }
    float q2 = pd0 * pd0 + pd1 * pd1 + ((d2 < D_DIM) ? pd2 * pd2 : 0.f);
    #pragma unroll
    for (int o = 16; o; o >>= 1) q2 += __shfl_xor_sync(0xffffffffu, q2, o);
    __syncthreads();
    if (lane == 0) s_red[wid] = q2;
    __syncthreads();
    if (tid == 0) {
        float t = 0.f;
        #pragma unroll
        for (int w = 0; w < 8; ++w) t += s_red[w];
        s_inorm = 1.0f / fmaxf(sqrtf(t), 1e-12f);
    }
    __syncthreads();
    const float innorm = s_inorm;

    // scatter into fragment layout, tf32-rounded
    #pragma unroll
    for (int u = 0; u < 3; ++u) {
        const int d = tid + u * 256;
        if (d < D_DIM) {
            const float v = (u == 0 ? pd0 : (u == 1 ? pd1 : pd2)) * innorm;
            const int s  = d >> 3;
            const int rm = d & 7;
            const int e  = rm >> 2;
            const int t  = rm & 3;
            const int ln = ((i & 7) << 2) | t;
            const int idx = (((s * 8 + (i >> 3)) * 32 + ln) * 2 + e);
            ((uint32_t*)g_Pf)[idx] = tf32_rna(v);
        }
    }
}

// ======================================================================
// Kernel 2: logits = query @ P^T * 10 via mma.sync m16n8k8 tf32.
//   Block 128 thr (4 warps). M-tile 128 (warp: 32 rows = 2 x m16),
//   full N = 64 (8 n-tiles), K-tile 32, cp.async double-buffered.
//   A smem: [128][36] floats (pitch 36 -> conflict-free frag reads).
//   B smem: 8KB/tile contiguous copy of pre-packed g_Pf fragments.
// ======================================================================
#define KT 32
#define NT (D_DIM / KT)                 // 20 K-tiles
#define A_PITCH 36
#define A_BYTES (128 * A_PITCH * 4)     // 18432
#define B_BYTES (KT * 64 * 4)           // 8192
#define OFF_B   (2 * A_BYTES)           // 36864
#define SMEM_TOTAL (OFF_B + 2 * B_BYTES) // 53248

__global__ void __launch_bounds__(128) logits_kernel(const float* __restrict__ qry,
                                                     float* __restrict__ out) {
    extern __shared__ __align__(16) char smem[];
    const uint32_t sbase = (uint32_t)__cvta_generic_to_shared(smem);
    const int tid  = threadIdx.x;
    const int lane = tid & 31;
    const int wid  = tid >> 5;
    const int g    = lane >> 2;         // group id (row within frag)
    const int t    = lane & 3;          // thread in group (col within frag)
    const size_t rowBase = (size_t)blockIdx.x * 128;

    float acc[2][8][4];
    #pragma unroll
    for (int u = 0; u < 2; ++u)
        #pragma unroll
        for (int j = 0; j < 8; ++j)
            #pragma unroll
            for (int c = 0; c < 4; ++c) acc[u][j][c] = 0.f;

    // ---- stage K-tile tt into buffer b ----
    auto stage = [&](int tt, int b) {
        const int k0 = tt * KT;
        const uint32_t aB = sbase + (uint32_t)b * A_BYTES;
        const uint32_t bB = sbase + OFF_B + (uint32_t)b * B_BYTES;
        #pragma unroll
        for (int jj = 0; jj < 8; ++jj) {
            const int c  = tid + jj * 128;   // 0..1023
            const int m  = c >> 3;           // row 0..127
            const int cw = c & 7;            // 16B chunk 0..7
            cp16(aB + (uint32_t)(m * (A_PITCH * 4) + cw * 16),
                 qry + (rowBase + m) * D_DIM + k0 + cw * 4);
        }
        const float* bsrc = g_Pf + (size_t)tt * (KT * 64);
        #pragma unroll
        for (int jj = 0; jj < 4; ++jj) {
            const int c = tid + jj * 128;    // 0..511
            cp16(bB + (uint32_t)c * 16, bsrc + c * 4);
        }
        CP_COMMIT();
    };

    // ---- compute on buffer b ----
    auto compute = [&](int b) {
        const float* sA = (const float*)(smem + (size_t)b * A_BYTES);
        const float* sB = (const float*)(smem + OFF_B + (size_t)b * B_BYTES);
        const int rw = wid * 32;
        #pragma unroll
        for (int s = 0; s < 4; ++s) {        // k8 steps within tile
            uint32_t bf[8][2];
            #pragma unroll
            for (int j = 0; j < 8; ++j) {
                const float2 v = *(const float2*)(sB + (s * 8 + j) * 64 + lane * 2);
                bf[j][0] = __float_as_uint(v.x);
                bf[j][1] = __float_as_uint(v.y);
            }
            uint32_t af[2][4];
            #pragma unroll
            for (int u = 0; u < 2; ++u) {
                const int base = (rw + u * 16 + g) * A_PITCH + s * 8 + t;
                af[u][0] = tf32_rna(sA[base]);
                af[u][1] = tf32_rna(sA[base + 8 * A_PITCH]);
                af[u][2] = tf32_rna(sA[base + 4]);
                af[u][3] = tf32_rna(sA[base + 8 * A_PITCH + 4]);
            }
            #pragma unroll
            for (int u = 0; u < 2; ++u)
                #pragma unroll
                for (int j = 0; j < 8; ++j)
                    mma_tf32(acc[u][j], af[u], bf[j][0], bf[j][1]);
        }
    };

    stage(0, 0);
    for (int tt = 0; tt < NT; ++tt) {
        const int b = tt & 1;
        if (tt + 1 < NT) {
            stage(tt + 1, b ^ 1);
            CP_WAIT(1);
        } else {
            CP_WAIT(0);
        }
        __syncthreads();
        compute(b);
        __syncthreads();
    }

    // ---- epilogue: scale x10, float2 stores ----
    #pragma unroll
    for (int u = 0; u < 2; ++u) {
        const size_t r0 = rowBase + wid * 32 + u * 16 + g;
        #pragma unroll
        for (int j = 0; j < 8; ++j) {
            const int c0 = j * 8 + t * 2;
            *(float2*)(out + r0 * 64 + c0) =
                make_float2(acc[u][j][0] * 10.f, acc[u][j][1] * 10.f);
            *(float2*)(out + (r0 + 8) * 64 + c0) =
                make_float2(acc[u][j][2] * 10.f, acc[u][j][3] * 10.f);
        }
    }
}

// ======================================================================
extern "C" void kernel_launch(void* const* d_in, const int* in_sizes, int n_in,
                              void* d_out, int out_size) {
    const float* emb = (const float*)d_in[0];
    float* out = (float*)d_out;

    cudaFuncSetAttribute(logits_kernel,
                         cudaFuncAttributeMaxDynamicSharedMemorySize, SMEM_TOTAL);

    proto_kernel<<<N_CLS, 256>>>(emb);

    const float* qry = emb + (size_t)SUP_ROWS * D_DIM;
    logits_kernel<<<NQ / 128, 128, SMEM_TOTAL>>>(qry, out);
}

// round 5
// speedup vs baseline: 4.2049x; 1.0514x over previous
#include <cuda_runtime.h>
#include <cstdint>

// Problem constants
#define N_CLS 64
#define K_SHOT 64
#define D_DIM 640
#define Q_PER 2048
#define NQ (N_CLS * Q_PER)        // 131072 query rows
#define SUP_ROWS (N_CLS * K_SHOT) // 4096 support rows

// proto_unnorm staging (class-major)
__device__ __align__(16) float g_pu[N_CLS * D_DIM];

// Prototypes pre-packed in mma.m16n8k8 B-fragment lane order, tf32-rounded:
//   g_Pf[(((s*8 + j)*32 + lane)*2 + e] = tf32(P[n][k]),
//   k = 8s + (lane&3) + 4e,  n = 8j + (lane>>2),  s = 0..79, j = 0..7.
__device__ __align__(16) float g_Pf[80 * 8 * 32 * 2];   // 160 KB

// ---------------- helpers ----------------
__device__ __forceinline__ uint32_t tf32_rna(float x) {
    uint32_t r;
    asm("cvt.rna.tf32.f32 %0, %1;" : "=r"(r) : "f"(x));
    return r;
}
__device__ __forceinline__ void cp16(uint32_t dst, const void* src) {
    asm volatile("cp.async.cg.shared.global [%0], [%1], 16;" :: "r"(dst), "l"(src));
}
#define CP_COMMIT() asm volatile("cp.async.commit_group;" ::: "memory")
#define CP_WAIT(n)  asm volatile("cp.async.wait_group %0;" :: "n"(n) : "memory")

__device__ __forceinline__ void mma_tf32(float* d, const uint32_t* a, uint32_t b0, uint32_t b1) {
    asm volatile(
        "mma.sync.aligned.m16n8k8.row.col.f32.tf32.tf32.f32 "
        "{%0,%1,%2,%3}, {%4,%5,%6,%7}, {%8,%9}, {%0,%1,%2,%3};"
        : "+f"(d[0]), "+f"(d[1]), "+f"(d[2]), "+f"(d[3])
        : "r"(a[0]), "r"(a[1]), "r"(a[2]), "r"(a[3]), "r"(b0), "r"(b1));
}

// ======================================================================
// Kernel 1a: proto_unnorm means. grid (5, 64): block (ch, i) computes
// g_pu[i][ch*128 .. +127]. 320 CTAs -> chip-wide latency hiding.
// ======================================================================
__global__ void __launch_bounds__(128) proto_mean(const float* __restrict__ emb) {
    const int i  = blockIdx.y;
    const int d  = blockIdx.x * 128 + threadIdx.x;
    const float* base = emb + (size_t)i * D_DIM + d;
    float s = 0.f;
    #pragma unroll 16
    for (int k = 0; k < K_SHOT; ++k)
        s += base[(size_t)k * (N_CLS * D_DIM)];
    g_pu[i * D_DIM + d] = s * (1.0f / 64.0f);
}

// ======================================================================
// Kernel 1b: rest of prototype computation. One block per class i.
// Support rows are L2-hot after proto_mean. Output -> g_Pf (tf32 frags).
// ======================================================================
__global__ void __launch_bounds__(256) proto_rest(const float* __restrict__ emb) {
    const int i    = blockIdx.x;
    const int tid  = threadIdx.x;
    const int lane = tid & 31;
    const int wid  = tid >> 5;

    __shared__ float s_pu[D_DIM];
    __shared__ float s_w[64];
    __shared__ float s_red[8];
    __shared__ float s_pn, s_isum, s_inorm;

    // ---- load proto_unnorm + its squared norm ----
    float pn2 = 0.f;
    for (int d = tid; d < D_DIM; d += 256) {
        float s = g_pu[i * D_DIM + d];
        s_pu[d] = s;
        pn2 += s * s;
    }
    #pragma unroll
    for (int o = 16; o; o >>= 1) pn2 += __shfl_xor_sync(0xffffffffu, pn2, o);
    if (lane == 0) s_red[wid] = pn2;
    __syncthreads();
    if (tid == 0) {
        float t = 0.f;
        #pragma unroll
        for (int w = 0; w < 8; ++w) t += s_red[w];
        s_pn = fmaxf(sqrtf(t), 1e-8f);
    }
    __syncthreads();
    const float p_norm = s_pn;

    // ---- per-shot cosine weights ----
    const float* blk = emb + (size_t)i * 64 * D_DIM;
    for (int j = wid; j < 64; j += 8) {
        const float* row = blk + (size_t)j * D_DIM;
        float dot = 0.f, s2 = 0.f;
        #pragma unroll 5
        for (int d = lane; d < D_DIM; d += 32) {
            float a = row[d];
            dot += a * s_pu[d];
            s2  += a * a;
        }
        #pragma unroll
        for (int o = 16; o; o >>= 1) {
            dot += __shfl_xor_sync(0xffffffffu, dot, o);
            s2  += __shfl_xor_sync(0xffffffffu, s2, o);
        }
        if (lane == 0) {
            float sn = fmaxf(sqrtf(s2), 1e-8f);
            s_w[j] = expf(dot / (p_norm * sn));
        }
    }
    __syncthreads();

    if (tid < 32) {
        float v = s_w[tid] + s_w[tid + 32];
        #pragma unroll
        for (int o = 16; o; o >>= 1) v += __shfl_xor_sync(0xffffffffu, v, o);
        if (tid == 0) s_isum = 1.0f / v;
    }
    __syncthreads();
    const float inv_sum = s_isum;

    // ---- weighted prototype + normalization ----
    float pd0 = 0.f, pd1 = 0.f, pd2 = 0.f;
    const int d0 = tid, d1 = tid + 256, d2 = tid + 512;
    #pragma unroll 4
    for (int j = 0; j < 64; ++j) {
        float wj = s_w[j] * inv_sum;
        const float* row = blk + (size_t)j * D_DIM;
        pd0 += wj * row[d0];
        pd1 += wj * row[d1];
        if (d2 < D_DIM) pd2 += wj * row[d2];
    }
    float q2 = pd0 * pd0 + pd1 * pd1 + ((d2 < D_DIM) ? pd2 * pd2 : 0.f);
    #pragma unroll
    for (int o = 16; o; o >>= 1) q2 += __shfl_xor_sync(0xffffffffu, q2, o);
    __syncthreads();
    if (lane == 0) s_red[wid] = q2;
    __syncthreads();
    if (tid == 0) {
        float t = 0.f;
        #pragma unroll
        for (int w = 0; w < 8; ++w) t += s_red[w];
        s_inorm = 1.0f / fmaxf(sqrtf(t), 1e-12f);
    }
    __syncthreads();
    const float innorm = s_inorm;

    // scatter into fragment layout, tf32-rounded
    #pragma unroll
    for (int u = 0; u < 3; ++u) {
        const int d = tid + u * 256;
        if (d < D_DIM) {
            const float v = (u == 0 ? pd0 : (u == 1 ? pd1 : pd2)) * innorm;
            const int s  = d >> 3;
            const int rm = d & 7;
            const int e  = rm >> 2;
            const int t  = rm & 3;
            const int ln = ((i & 7) << 2) | t;
            const int idx = (((s * 8 + (i >> 3)) * 32 + ln) * 2 + e);
            ((uint32_t*)g_Pf)[idx] = tf32_rna(v);
        }
    }
}

// ======================================================================
// Kernel 2: logits = query @ P^T * 10 via mma.sync m16n8k8 tf32.
//   Block 128 thr (4 warps), M-tile 128, N=64, KT=16, DEPTH-4 cp.async
//   ring (3 tiles in flight). A smem [128][20] pitch (conflict-free),
//   B smem 4KB/tile contiguous pre-packed fragments. 4 CTAs/SM pinned.
// ======================================================================
#define KT 16
#define NT (D_DIM / KT)                 // 40 K-tiles
#define A_PITCH 20
#define A_BYTES (128 * A_PITCH * 4)     // 10240
#define B_BYTES (KT * 64 * 4)           // 4096
#define STAGE_BYTES (A_BYTES + B_BYTES) // 14336
#define SMEM_TOTAL (4 * STAGE_BYTES)    // 57344

__global__ void __launch_bounds__(128, 4) logits_kernel(const float* __restrict__ qry,
                                                        float* __restrict__ out) {
    extern __shared__ __align__(16) char smem[];
    const uint32_t sbase = (uint32_t)__cvta_generic_to_shared(smem);
    const int tid  = threadIdx.x;
    const int lane = tid & 31;
    const int wid  = tid >> 5;
    const int g    = lane >> 2;         // row within frag group
    const int t    = lane & 3;          // col within frag group
    const size_t rowBase = (size_t)blockIdx.x * 128;

    float acc[2][8][4];
    #pragma unroll
    for (int u = 0; u < 2; ++u)
        #pragma unroll
        for (int j = 0; j < 8; ++j)
            #pragma unroll
            for (int c = 0; c < 4; ++c) acc[u][j][c] = 0.f;

    // ---- stage K-tile tt into ring slot ----
    auto stage = [&](int tt) {
        const int k0 = tt * KT;
        const uint32_t sB = sbase + (uint32_t)(tt & 3) * STAGE_BYTES;
        #pragma unroll
        for (int jj = 0; jj < 4; ++jj) {
            const int c  = tid + jj * 128;   // 0..511
            const int m  = c >> 2;           // row 0..127
            const int cw = c & 3;            // 16B chunk 0..3
            cp16(sB + (uint32_t)(m * (A_PITCH * 4) + cw * 16),
                 qry + (rowBase + m) * D_DIM + k0 + cw * 4);
        }
        const float* bsrc = g_Pf + (size_t)tt * (KT * 64);
        #pragma unroll
        for (int jj = 0; jj < 2; ++jj) {
            const int c = tid + jj * 128;    // 0..255
            cp16(sB + (uint32_t)A_BYTES + (uint32_t)c * 16, bsrc + c * 4);
        }
        CP_COMMIT();
    };

    // ---- compute on ring slot of tile tt ----
    auto compute = [&](int tt) {
        const char* stg = smem + (size_t)(tt & 3) * STAGE_BYTES;
        const float* sA = (const float*)stg;
        const float* sB = (const float*)(stg + A_BYTES);
        const int rw = wid * 32;
        #pragma unroll
        for (int s = 0; s < KT / 8; ++s) {   // 2 k8-steps
            uint32_t bf[8][2];
            #pragma unroll
            for (int j = 0; j < 8; ++j) {
                const float2 v = *(const float2*)(sB + (s * 8 + j) * 64 + lane * 2);
                bf[j][0] = __float_as_uint(v.x);
                bf[j][1] = __float_as_uint(v.y);
            }
            uint32_t af[2][4];
            #pragma unroll
            for (int u = 0; u < 2; ++u) {
                const int base = (rw + u * 16 + g) * A_PITCH + s * 8 + t;
                af[u][0] = tf32_rna(sA[base]);
                af[u][1] = tf32_rna(sA[base + 8 * A_PITCH]);
                af[u][2] = tf32_rna(sA[base + 4]);
                af[u][3] = tf32_rna(sA[base + 8 * A_PITCH + 4]);
            }
            #pragma unroll
            for (int u = 0; u < 2; ++u)
                #pragma unroll
                for (int j = 0; j < 8; ++j)
                    mma_tf32(acc[u][j], af[u], bf[j][0], bf[j][1]);
        }
    };

    stage(0); stage(1); stage(2);
    for (int tt = 0; tt < NT; ++tt) {
        if (tt + 3 < NT) { stage(tt + 3); CP_WAIT(3); }
        else if (tt + 2 < NT) { CP_WAIT(2); }
        else if (tt + 1 < NT) { CP_WAIT(1); }
        else { CP_WAIT(0); }
        __syncthreads();
        compute(tt);
        __syncthreads();
    }

    // ---- epilogue: scale x10, float2 stores ----
    #pragma unroll
    for (int u = 0; u < 2; ++u) {
        const size_t r0 = rowBase + wid * 32 + u * 16 + g;
        #pragma unroll
        for (int j = 0; j < 8; ++j) {
            const int c0 = j * 8 + t * 2;
            *(float2*)(out + r0 * 64 + c0) =
                make_float2(acc[u][j][0] * 10.f, acc[u][j][1] * 10.f);
            *(float2*)(out + (r0 + 8) * 64 + c0) =
                make_float2(acc[u][j][2] * 10.f, acc[u][j][3] * 10.f);
        }
    }
}

// ======================================================================
extern "C" void kernel_launch(void* const* d_in, const int* in_sizes, int n_in,
                              void* d_out, int out_size) {
    const float* emb = (const float*)d_in[0];
    float* out = (float*)d_out;

    cudaFuncSetAttribute(logits_kernel,
                         cudaFuncAttributeMaxDynamicSharedMemorySize, SMEM_TOTAL);

    proto_mean<<<dim3(5, 64), 128>>>(emb);
    proto_rest<<<N_CLS, 256>>>(emb);

    const float* qry = emb + (size_t)SUP_ROWS * D_DIM;
    logits_kernel<<<NQ / 128, 128, SMEM_TOTAL>>>(qry, out);
}

// round 6
// speedup vs baseline: 4.5522x; 1.0826x over previous
#include <cuda_runtime.h>
#include <cstdint>

// Problem constants
#define N_CLS 64
#define K_SHOT 64
#define D_DIM 640
#define Q_PER 2048
#define NQ (N_CLS * Q_PER)        // 131072 query rows
#define SUP_ROWS (N_CLS * K_SHOT) // 4096 support rows

// Staging buffers
__device__ __align__(16) float g_pu[N_CLS * D_DIM];   // proto_unnorm
__device__ __align__(16) float g_dis[N_CLS * K_SHOT]; // softmax numerators

// Prototypes pre-packed in mma.m16n8k8 B-fragment lane order, tf32-rounded:
//   g_Pf[(((s*8 + j)*32 + lane)*2 + e] = tf32(P[n][k]),
//   k = 8s + (lane&3) + 4e,  n = 8j + (lane>>2),  s = 0..79, j = 0..7.
__device__ __align__(16) float g_Pf[80 * 8 * 32 * 2];   // 160 KB

// ---------------- helpers ----------------
__device__ __forceinline__ uint32_t tf32_rna(float x) {
    uint32_t r;
    asm("cvt.rna.tf32.f32 %0, %1;" : "=r"(r) : "f"(x));
    return r;
}
__device__ __forceinline__ void cp16(uint32_t dst, const void* src) {
    asm volatile("cp.async.cg.shared.global [%0], [%1], 16;" :: "r"(dst), "l"(src));
}
#define CP_COMMIT() asm volatile("cp.async.commit_group;" ::: "memory")
#define CP_WAIT(n)  asm volatile("cp.async.wait_group %0;" :: "n"(n) : "memory")

__device__ __forceinline__ void mma_tf32(float* d, const uint32_t* a, uint32_t b0, uint32_t b1) {
    asm volatile(
        "mma.sync.aligned.m16n8k8.row.col.f32.tf32.tf32.f32 "
        "{%0,%1,%2,%3}, {%4,%5,%6,%7}, {%8,%9}, {%0,%1,%2,%3};"
        : "+f"(d[0]), "+f"(d[1]), "+f"(d[2]), "+f"(d[3])
        : "r"(a[0]), "r"(a[1]), "r"(a[2]), "r"(a[3]), "r"(b0), "r"(b1));
}

// ======================================================================
// Kernel 1a: proto_unnorm means. grid (5, 64); unroll-32 for deep MLP.
// ======================================================================
__global__ void __launch_bounds__(128) proto_mean(const float* __restrict__ emb) {
    const int i  = blockIdx.y;
    const int d  = blockIdx.x * 128 + threadIdx.x;
    const float* base = emb + (size_t)i * D_DIM + d;
    float s = 0.f;
    #pragma unroll 32
    for (int k = 0; k < K_SHOT; ++k)
        s += base[(size_t)k * (N_CLS * D_DIM)];
    g_pu[i * D_DIM + d] = s * (1.0f / 64.0f);
}

// ======================================================================
// Kernel 1b: cosine-softmax numerators. grid (8, 64): block (jg, i),
// 8 warps, warp handles row j = jg*8 + wid. Writes g_dis[i][j].
// ======================================================================
__global__ void __launch_bounds__(256) proto_w(const float* __restrict__ emb) {
    const int i    = blockIdx.y;
    const int tid  = threadIdx.x;
    const int lane = tid & 31;
    const int wid  = tid >> 5;
    const int j    = blockIdx.x * 8 + wid;

    __shared__ float s_pu[D_DIM];
    __shared__ float s_red[8];
    __shared__ float s_pn;

    float pn2 = 0.f;
    for (int d = tid; d < D_DIM; d += 256) {
        float s = g_pu[i * D_DIM + d];
        s_pu[d] = s;
        pn2 += s * s;
    }
    #pragma unroll
    for (int o = 16; o; o >>= 1) pn2 += __shfl_xor_sync(0xffffffffu, pn2, o);
    if (lane == 0) s_red[wid] = pn2;
    __syncthreads();
    if (tid == 0) {
        float t = 0.f;
        #pragma unroll
        for (int w = 0; w < 8; ++w) t += s_red[w];
        s_pn = fmaxf(sqrtf(t), 1e-8f);
    }
    __syncthreads();
    const float p_norm = s_pn;

    const float* row = emb + ((size_t)i * 64 + j) * D_DIM;
    float dot = 0.f, s2 = 0.f;
    #pragma unroll 5
    for (int d = lane; d < D_DIM; d += 32) {
        float a = row[d];
        dot += a * s_pu[d];
        s2  += a * a;
    }
    #pragma unroll
    for (int o = 16; o; o >>= 1) {
        dot += __shfl_xor_sync(0xffffffffu, dot, o);
        s2  += __shfl_xor_sync(0xffffffffu, s2, o);
    }
    if (lane == 0) {
        float sn = fmaxf(sqrtf(s2), 1e-8f);
        g_dis[i * 64 + j] = expf(dot / (p_norm * sn));
    }
}

// ======================================================================
// Kernel 1c: weighted prototype + norm + tf32 fragment scatter.
// grid (64), 640 threads (thread = dimension d). Support is L2-hot.
// ======================================================================
__global__ void __launch_bounds__(640) proto_pd(const float* __restrict__ emb) {
    const int i    = blockIdx.x;
    const int tid  = threadIdx.x;   // = d
    const int lane = tid & 31;
    const int wid  = tid >> 5;      // 0..19

    __shared__ float s_dis[64];
    __shared__ float s_red[20];
    __shared__ float s_isum, s_inorm;

    if (tid < 64) s_dis[tid] = g_dis[i * 64 + tid];
    __syncthreads();
    if (tid < 32) {
        float v = s_dis[tid] + s_dis[tid + 32];
        #pragma unroll
        for (int o = 16; o; o >>= 1) v += __shfl_xor_sync(0xffffffffu, v, o);
        if (tid == 0) s_isum = 1.0f / v;
    }
    __syncthreads();
    const float inv_sum = s_isum;

    const float* blk = emb + (size_t)i * 64 * D_DIM + tid;
    float pd = 0.f;
    #pragma unroll 8
    for (int j = 0; j < 64; ++j)
        pd += (s_dis[j] * inv_sum) * blk[(size_t)j * D_DIM];

    float q2 = pd * pd;
    #pragma unroll
    for (int o = 16; o; o >>= 1) q2 += __shfl_xor_sync(0xffffffffu, q2, o);
    if (lane == 0) s_red[wid] = q2;
    __syncthreads();
    if (tid == 0) {
        float t = 0.f;
        #pragma unroll
        for (int w = 0; w < 20; ++w) t += s_red[w];
        s_inorm = 1.0f / fmaxf(sqrtf(t), 1e-12f);
    }
    __syncthreads();

    const float v = pd * s_inorm;
    const int s   = tid >> 3;
    const int rm  = tid & 7;
    const int e   = rm >> 2;
    const int t4  = rm & 3;
    const int ln  = ((i & 7) << 2) | t4;
    const int idx = (((s * 8 + (i >> 3)) * 32 + ln) * 2 + e);
    ((uint32_t*)g_Pf)[idx] = tf32_rna(v);
}

// ======================================================================
// Kernel 2: logits = query @ P^T * 10 via mma.sync m16n8k8 tf32.
//   Block 128 thr (4 warps), M-tile 128, N=64, KT=64, double-buffered.
//   A rows now load as 256B contiguous granules (DRAM-page friendly);
//   only 10 barrier-gated tiles. A pitch 68 -> conflict-free frags.
// ======================================================================
#define KT 64
#define NT (D_DIM / KT)                 // 10 K-tiles
#define A_PITCH 68
#define A_BYTES (128 * A_PITCH * 4)     // 34816
#define B_BYTES (KT * 64 * 4)           // 16384
#define STAGE_BYTES (A_BYTES + B_BYTES) // 51200
#define SMEM_TOTAL (2 * STAGE_BYTES)    // 102400

__global__ void __launch_bounds__(128, 2) logits_kernel(const float* __restrict__ qry,
                                                        float* __restrict__ out) {
    extern __shared__ __align__(16) char smem[];
    const uint32_t sbase = (uint32_t)__cvta_generic_to_shared(smem);
    const int tid  = threadIdx.x;
    const int lane = tid & 31;
    const int wid  = tid >> 5;
    const int g    = lane >> 2;
    const int t    = lane & 3;
    const size_t rowBase = (size_t)blockIdx.x * 128;

    float acc[2][8][4];
    #pragma unroll
    for (int u = 0; u < 2; ++u)
        #pragma unroll
        for (int j = 0; j < 8; ++j)
            #pragma unroll
            for (int c = 0; c < 4; ++c) acc[u][j][c] = 0.f;

    // ---- stage K-tile tt into buffer (tt&1) ----
    auto stage = [&](int tt) {
        const int k0 = tt * KT;
        const uint32_t sB = sbase + (uint32_t)(tt & 1) * STAGE_BYTES;
        #pragma unroll
        for (int jj = 0; jj < 16; ++jj) {
            const int c  = tid + jj * 128;   // 0..2047
            const int m  = c >> 4;           // row 0..127
            const int cw = c & 15;           // 16B chunk 0..15
            cp16(sB + (uint32_t)(m * (A_PITCH * 4) + cw * 16),
                 qry + (rowBase + m) * D_DIM + k0 + cw * 4);
        }
        const float* bsrc = g_Pf + (size_t)tt * (KT * 64);
        #pragma unroll
        for (int jj = 0; jj < 8; ++jj) {
            const int c = tid + jj * 128;    // 0..1023
            cp16(sB + (uint32_t)A_BYTES + (uint32_t)c * 16, bsrc + c * 4);
        }
        CP_COMMIT();
    };

    // ---- compute on buffer of tile tt ----
    auto compute = [&](int tt) {
        const char* stg = smem + (size_t)(tt & 1) * STAGE_BYTES;
        const float* sA = (const float*)stg;
        const float* sB = (const float*)(stg + A_BYTES);
        const int rw = wid * 32;
        #pragma unroll
        for (int s = 0; s < KT / 8; ++s) {   // 8 k8-steps
            uint32_t bf[8][2];
            #pragma unroll
            for (int j = 0; j < 8; ++j) {
                const float2 v = *(const float2*)(sB + (s * 8 + j) * 64 + lane * 2);
                bf[j][0] = __float_as_uint(v.x);
                bf[j][1] = __float_as_uint(v.y);
            }
            uint32_t af[2][4];
            #pragma unroll
            for (int u = 0; u < 2; ++u) {
                const int base = (rw + u * 16 + g) * A_PITCH + s * 8 + t;
                af[u][0] = tf32_rna(sA[base]);
                af[u][1] = tf32_rna(sA[base + 8 * A_PITCH]);
                af[u][2] = tf32_rna(sA[base + 4]);
                af[u][3] = tf32_rna(sA[base + 8 * A_PITCH + 4]);
            }
            #pragma unroll
            for (int u = 0; u < 2; ++u)
                #pragma unroll
                for (int j = 0; j < 8; ++j)
                    mma_tf32(acc[u][j], af[u], bf[j][0], bf[j][1]);
        }
    };

    stage(0);
    for (int tt = 0; tt < NT; ++tt) {
        if (tt + 1 < NT) { stage(tt + 1); CP_WAIT(1); }
        else             { CP_WAIT(0); }
        __syncthreads();
        compute(tt);
        __syncthreads();
    }

    // ---- epilogue: scale x10, float2 stores ----
    #pragma unroll
    for (int u = 0; u < 2; ++u) {
        const size_t r0 = rowBase + wid * 32 + u * 16 + g;
        #pragma unroll
        for (int j = 0; j < 8; ++j) {
            const int c0 = j * 8 + t * 2;
            *(float2*)(out + r0 * 64 + c0) =
                make_float2(acc[u][j][0] * 10.f, acc[u][j][1] * 10.f);
            *(float2*)(out + (r0 + 8) * 64 + c0) =
                make_float2(acc[u][j][2] * 10.f, acc[u][j][3] * 10.f);
        }
    }
}

// ======================================================================
extern "C" void kernel_launch(void* const* d_in, const int* in_sizes, int n_in,
                              void* d_out, int out_size) {
    const float* emb = (const float*)d_in[0];
    float* out = (float*)d_out;

    cudaFuncSetAttribute(logits_kernel,
                         cudaFuncAttributeMaxDynamicSharedMemorySize, SMEM_TOTAL);

    proto_mean<<<dim3(5, 64), 128>>>(emb);
    proto_w<<<dim3(8, 64), 256>>>(emb);
    proto_pd<<<N_CLS, 640>>>(emb);

    const float* qry = emb + (size_t)SUP_ROWS * D_DIM;
    logits_kernel<<<NQ / 128, 128, SMEM_TOTAL>>>(qry, out);
}

// round 7
// speedup vs baseline: 5.4382x; 1.1946x over previous
#include <cuda_runtime.h>
#include <cstdint>

// Problem constants
#define N_CLS 64
#define K_SHOT 64
#define D_DIM 640
#define Q_PER 2048
#define NQ (N_CLS * Q_PER)        // 131072 query rows
#define SUP_ROWS (N_CLS * K_SHOT) // 4096 support rows

typedef unsigned long long ull;

// Staging buffers
__device__ __align__(16) float g_pu[N_CLS * D_DIM];   // proto_unnorm
__device__ __align__(16) float g_dis[N_CLS * K_SHOT]; // softmax numerators

// Prototypes pre-packed as fp16x2 in mma.m16n8k16 B-fragment order:
//   g_Ph[((s*8 + j)*32 + l)*2 + r] = {f16(P[n][k_e0]), f16(P[n][k_e1])},
//   k = 16s + 2t + e + 8r (t = l&3), n = 8j + (l>>2),  s = 0..39.
__device__ __align__(16) uint32_t g_Ph[40 * 8 * 32 * 2];   // 80 KB

// ---------------- helpers ----------------
__device__ __forceinline__ uint32_t f16x2_from(float lo, float hi) {
    uint32_t r;
    asm("cvt.rn.f16x2.f32 %0, %1, %2;" : "=r"(r) : "f"(hi), "f"(lo));
    return r;
}
__device__ __forceinline__ void cp16(uint32_t dst, const void* src) {
    asm volatile("cp.async.cg.shared.global [%0], [%1], 16;" :: "r"(dst), "l"(src));
}
#define CP_COMMIT() asm volatile("cp.async.commit_group;" ::: "memory")
#define CP_WAIT(n)  asm volatile("cp.async.wait_group %0;" :: "n"(n) : "memory")

__device__ __forceinline__ void mma_f16(float* d, const uint32_t* a, uint32_t b0, uint32_t b1) {
    asm volatile(
        "mma.sync.aligned.m16n8k16.row.col.f32.f16.f16.f32 "
        "{%0,%1,%2,%3}, {%4,%5,%6,%7}, {%8,%9}, {%0,%1,%2,%3};"
        : "+f"(d[0]), "+f"(d[1]), "+f"(d[2]), "+f"(d[3])
        : "r"(a[0]), "r"(a[1]), "r"(a[2]), "r"(a[3]), "r"(b0), "r"(b1));
}

// ======================================================================
// Kernel 1a: proto_unnorm means. grid (5, 64); unroll-32 for deep MLP.
// ======================================================================
__global__ void __launch_bounds__(128) proto_mean(const float* __restrict__ emb) {
    const int i  = blockIdx.y;
    const int d  = blockIdx.x * 128 + threadIdx.x;
    const float* base = emb + (size_t)i * D_DIM + d;
    float s = 0.f;
    #pragma unroll 32
    for (int k = 0; k < K_SHOT; ++k)
        s += base[(size_t)k * (N_CLS * D_DIM)];
    g_pu[i * D_DIM + d] = s * (1.0f / 64.0f);
}

// ======================================================================
// Kernel 1b: cosine-softmax numerators. grid (8, 64); warp = support row.
// ======================================================================
__global__ void __launch_bounds__(256) proto_w(const float* __restrict__ emb) {
    const int i    = blockIdx.y;
    const int tid  = threadIdx.x;
    const int lane = tid & 31;
    const int wid  = tid >> 5;
    const int j    = blockIdx.x * 8 + wid;

    __shared__ float s_pu[D_DIM];
    __shared__ float s_red[8];
    __shared__ float s_pn;

    float pn2 = 0.f;
    for (int d = tid; d < D_DIM; d += 256) {
        float s = g_pu[i * D_DIM + d];
        s_pu[d] = s;
        pn2 += s * s;
    }
    #pragma unroll
    for (int o = 16; o; o >>= 1) pn2 += __shfl_xor_sync(0xffffffffu, pn2, o);
    if (lane == 0) s_red[wid] = pn2;
    __syncthreads();
    if (tid == 0) {
        float t = 0.f;
        #pragma unroll
        for (int w = 0; w < 8; ++w) t += s_red[w];
        s_pn = fmaxf(sqrtf(t), 1e-8f);
    }
    __syncthreads();
    const float p_norm = s_pn;

    const float* row = emb + ((size_t)i * 64 + j) * D_DIM;
    float dot = 0.f, s2 = 0.f;
    #pragma unroll 5
    for (int d = lane; d < D_DIM; d += 32) {
        float a = row[d];
        dot += a * s_pu[d];
        s2  += a * a;
    }
    #pragma unroll
    for (int o = 16; o; o >>= 1) {
        dot += __shfl_xor_sync(0xffffffffu, dot, o);
        s2  += __shfl_xor_sync(0xffffffffu, s2, o);
    }
    if (lane == 0) {
        float sn = fmaxf(sqrtf(s2), 1e-8f);
        g_dis[i * 64 + j] = expf(dot / (p_norm * sn));
    }
}

// ======================================================================
// Kernel 1c: weighted prototype + norm + fp16 fragment scatter.
// grid (64), 640 threads (thread = dimension d). Support is L2-hot.
// ======================================================================
__global__ void __launch_bounds__(640) proto_pd(const float* __restrict__ emb) {
    const int i    = blockIdx.x;
    const int tid  = threadIdx.x;   // = d
    const int lane = tid & 31;
    const int wid  = tid >> 5;      // 0..19

    __shared__ float s_dis[64];
    __shared__ float s_p[D_DIM];
    __shared__ float s_red[20];
    __shared__ float s_isum, s_inorm;

    if (tid < 64) s_dis[tid] = g_dis[i * 64 + tid];
    __syncthreads();
    if (tid < 32) {
        float v = s_dis[tid] + s_dis[tid + 32];
        #pragma unroll
        for (int o = 16; o; o >>= 1) v += __shfl_xor_sync(0xffffffffu, v, o);
        if (tid == 0) s_isum = 1.0f / v;
    }
    __syncthreads();
    const float inv_sum = s_isum;

    const float* blk = emb + (size_t)i * 64 * D_DIM + tid;
    float pd = 0.f;
    #pragma unroll 8
    for (int j = 0; j < 64; ++j)
        pd += (s_dis[j] * inv_sum) * blk[(size_t)j * D_DIM];

    float q2 = pd * pd;
    #pragma unroll
    for (int o = 16; o; o >>= 1) q2 += __shfl_xor_sync(0xffffffffu, q2, o);
    if (lane == 0) s_red[wid] = q2;
    __syncthreads();
    if (tid == 0) {
        float t = 0.f;
        #pragma unroll
        for (int w = 0; w < 20; ++w) t += s_red[w];
        s_inorm = 1.0f / fmaxf(sqrtf(t), 1e-12f);
    }
    __syncthreads();
    s_p[tid] = pd * s_inorm;
    __syncthreads();

    // pack pairs into fp16 B-fragment layout: tid2 = s*8 + t*2 + r
    if (tid < 320) {
        const int s  = tid >> 3;
        const int t4 = (tid & 7) >> 1;
        const int r  = tid & 1;
        const int k0 = 16 * s + 2 * t4 + 8 * r;
        const int ln = 4 * (i & 7) + t4;
        const int idx = ((s * 8 + (i >> 3)) * 32 + ln) * 2 + r;
        g_Ph[idx] = f16x2_from(s_p[k0], s_p[k0 + 1]);
    }
}

// ======================================================================
// Kernel 2: logits = query @ P^T * 10 via mma.sync m16n8k16 fp16.
//   Block 256 thr (8 warps), M-tile 128 (warp = one m16 tile), N=64,
//   KT=64 (4 k16-steps), double-buffered cp.async.
//   A smem fp32 [128][72] (pitch 72 -> conflict-free float2 frag loads,
//   (4g+t) distinct mod 16 per phase); B smem = 8KB/tile pre-packed
//   fp16 fragments (1 LDS.64 per n-tile). A cvt'd fp32->f16x2 on load.
// ======================================================================
#define KT 64
#define NT (D_DIM / KT)                 // 10 K-tiles
#define A_PITCH 72
#define A_BYTES (128 * A_PITCH * 4)     // 36864
#define B_BYTES (4 * 8 * 32 * 2 * 4)    // 8192 (4 k16-steps)
#define STAGE_BYTES (A_BYTES + B_BYTES) // 45056
#define SMEM_TOTAL (2 * STAGE_BYTES)    // 90112

__global__ void __launch_bounds__(256, 2) logits_kernel(const float* __restrict__ qry,
                                                        float* __restrict__ out) {
    extern __shared__ __align__(16) char smem[];
    const uint32_t sbase = (uint32_t)__cvta_generic_to_shared(smem);
    const int tid  = threadIdx.x;
    const int lane = tid & 31;
    const int wid  = tid >> 5;          // warp = m16 tile 0..7
    const int g    = lane >> 2;
    const int t    = lane & 3;
    const size_t rowBase = (size_t)blockIdx.x * 128;

    float acc[8][4];
    #pragma unroll
    for (int j = 0; j < 8; ++j)
        #pragma unroll
        for (int c = 0; c < 4; ++c) acc[j][c] = 0.f;

    // ---- stage K-tile tt into buffer (tt&1) ----
    auto stage = [&](int tt) {
        const int k0 = tt * KT;
        const uint32_t sB = sbase + (uint32_t)(tt & 1) * STAGE_BYTES;
        #pragma unroll
        for (int jj = 0; jj < 8; ++jj) {
            const int c  = tid + jj * 256;   // 0..2047
            const int m  = c >> 4;           // row 0..127
            const int cw = c & 15;           // 16B chunk 0..15
            cp16(sB + (uint32_t)(m * (A_PITCH * 4) + cw * 16),
                 qry + (rowBase + m) * D_DIM + k0 + cw * 4);
        }
        const char* bsrc = (const char*)g_Ph + (size_t)tt * B_BYTES;
        #pragma unroll
        for (int jj = 0; jj < 2; ++jj) {
            const int c = tid + jj * 256;    // 0..511
            cp16(sB + (uint32_t)A_BYTES + (uint32_t)c * 16, bsrc + c * 16);
        }
        CP_COMMIT();
    };

    // ---- compute on buffer of tile tt ----
    auto compute = [&](int tt) {
        const char* stg = smem + (size_t)(tt & 1) * STAGE_BYTES;
        const float* sA = (const float*)stg;
        const uint32_t* sBh = (const uint32_t*)(stg + A_BYTES);
        #pragma unroll
        for (int s = 0; s < 4; ++s) {        // k16-steps
            // B fragments: one LDS.64 per n-tile (contiguous reg pair)
            uint32_t bf[8][2];
            #pragma unroll
            for (int j = 0; j < 8; ++j) {
                const ull v = *(const ull*)(sBh + ((s * 8 + j) * 32 + lane) * 2);
                bf[j][0] = (uint32_t)v;
                bf[j][1] = (uint32_t)(v >> 32);
            }
            // A fragment: rows g, g+8; k pairs (2t,2t+1) and (+8)
            const float* rg = sA + (wid * 16 + g) * A_PITCH + s * 16;
            const float* rh = rg + 8 * A_PITCH;
            const float2 p0 = *(const float2*)(rg + 2 * t);
            const float2 p1 = *(const float2*)(rg + 2 * t + 8);
            const float2 q0 = *(const float2*)(rh + 2 * t);
            const float2 q1 = *(const float2*)(rh + 2 * t + 8);
            uint32_t af[4];
            af[0] = f16x2_from(p0.x, p0.y);
            af[1] = f16x2_from(q0.x, q0.y);
            af[2] = f16x2_from(p1.x, p1.y);
            af[3] = f16x2_from(q1.x, q1.y);
            #pragma unroll
            for (int j = 0; j < 8; ++j)
                mma_f16(acc[j], af, bf[j][0], bf[j][1]);
        }
    };

    stage(0);
    for (int tt = 0; tt < NT; ++tt) {
        if (tt + 1 < NT) { stage(tt + 1); CP_WAIT(1); }
        else             { CP_WAIT(0); }
        __syncthreads();
        compute(tt);
        __syncthreads();
    }

    // ---- epilogue: scale x10, float2 stores ----
    const size_t r0 = rowBase + wid * 16 + g;
    #pragma unroll
    for (int j = 0; j < 8; ++j) {
        const int c0 = j * 8 + t * 2;
        *(float2*)(out + r0 * 64 + c0) =
            make_float2(acc[j][0] * 10.f, acc[j][1] * 10.f);
        *(float2*)(out + (r0 + 8) * 64 + c0) =
            make_float2(acc[j][2] * 10.f, acc[j][3] * 10.f);
    }
}

// ======================================================================
extern "C" void kernel_launch(void* const* d_in, const int* in_sizes, int n_in,
                              void* d_out, int out_size) {
    const float* emb = (const float*)d_in[0];
    float* out = (float*)d_out;

    cudaFuncSetAttribute(logits_kernel,
                         cudaFuncAttributeMaxDynamicSharedMemorySize, SMEM_TOTAL);

    proto_mean<<<dim3(5, 64), 128>>>(emb);
    proto_w<<<dim3(8, 64), 256>>>(emb);
    proto_pd<<<N_CLS, 640>>>(emb);

    const float* qry = emb + (size_t)SUP_ROWS * D_DIM;
    logits_kernel<<<NQ / 128, 256, SMEM_TOTAL>>>(qry, out);
}